// round 6
// baseline (speedup 1.0000x reference)
#include <cuda_runtime.h>
#include <math.h>

#define DIM_EI  4096
#define DIM_CA3 8192
#define DIM_CA1 8192
#define DIM_EO  4096

static constexpr float BETA  = 10.0f;
static constexpr float ALPHA = 0.01f;

// ---------------- device scratch ----------------
__device__ float g_h1[DIM_CA3];
__device__ float g_h3[DIM_CA1];
__device__ float g_h4[DIM_EO];
__device__ float g_xca3[DIM_CA3];
__device__ float g_IS[DIM_CA1];
__device__ float g_xca1[DIM_CA1];
__device__ int   g_nnz_idx[DIM_CA3];   // nonzeros of x_ca3
__device__ float g_nnz_val[DIM_CA3];
__device__ int   g_nnz_cnt;
__device__ int   g_act_idx[DIM_CA1];   // rows with IS > 0
__device__ int   g_act_cnt;
__device__ unsigned g_ctr_out;         // arrival counter; self-resets

// ---------------- helpers ----------------
__device__ __forceinline__ unsigned f2u(float f) {
    unsigned u = __float_as_uint(f);
    return (u & 0x80000000u) ? ~u : (u | 0x80000000u);
}
__device__ __forceinline__ float u2f(unsigned u) {
    return __uint_as_float((u & 0x80000000u) ? (u & 0x7fffffffu) : ~u);
}
__device__ __forceinline__ float sigm(float z) { return 1.0f / (1.0f + expf(-z)); }

// Exact K-th largest via 4-pass radix-256 over per-thread register values.
// blockDim.x >= 256; all threads call.
template<int M>
__device__ float kth_largest_radix256(const unsigned* uv, int K) {
    __shared__ unsigned s_hist[256];
    __shared__ int s_bin, s_k;
    unsigned prefix = 0;
    int k = K;
    #pragma unroll
    for (int shift = 24; shift >= 0; shift -= 8) {
        for (int b = threadIdx.x; b < 256; b += blockDim.x) s_hist[b] = 0;
        __syncthreads();
        unsigned hi = (shift == 24) ? 0u : (0xFFFFFFFFu << (shift + 8));
        #pragma unroll
        for (int j = 0; j < M; j++) {
            unsigned u = uv[j];
            if ((u & hi) == prefix) atomicAdd(&s_hist[(u >> shift) & 255], 1u);
        }
        __syncthreads();
        #pragma unroll
        for (int d = 1; d < 256; d <<= 1) {
            unsigned add = 0;
            if (threadIdx.x < 256)
                add = (threadIdx.x + d < 256) ? s_hist[threadIdx.x + d] : 0u;
            __syncthreads();
            if (threadIdx.x < 256) s_hist[threadIdx.x] += add;
            __syncthreads();
        }
        if (threadIdx.x < 256) {
            unsigned ge = s_hist[threadIdx.x];
            unsigned gt = (threadIdx.x == 255) ? 0u : s_hist[threadIdx.x + 1];
            if (ge >= (unsigned)k && gt < (unsigned)k) { s_bin = threadIdx.x; s_k = k - (int)gt; }
        }
        __syncthreads();
        prefix |= ((unsigned)s_bin) << shift;
        k = s_k;
        __syncthreads();
    }
    return u2f(prefix);
}

// Exact K-th largest of x[0..n) reading from global each pass (for small n).
__device__ float kth_global_256(const float* __restrict__ x, int n, int K) {
    __shared__ unsigned s_hist[256];
    __shared__ int s_bin, s_k;
    int tid = threadIdx.x;
    unsigned prefix = 0;
    int k = K;
    #pragma unroll
    for (int shift = 24; shift >= 0; shift -= 8) {
        s_hist[tid] = 0;
        __syncthreads();
        unsigned hi = (shift == 24) ? 0u : (0xFFFFFFFFu << (shift + 8));
        for (int i = tid; i < n; i += 256) {
            unsigned u = f2u(x[i]);
            if ((u & hi) == prefix) atomicAdd(&s_hist[(u >> shift) & 255], 1u);
        }
        __syncthreads();
        #pragma unroll
        for (int d = 1; d < 256; d <<= 1) {
            unsigned add = (tid + d < 256) ? s_hist[tid + d] : 0u;
            __syncthreads();
            s_hist[tid] += add;
            __syncthreads();
        }
        {
            unsigned ge = s_hist[tid];
            unsigned gt = (tid == 255) ? 0u : s_hist[tid + 1];
            if (ge >= (unsigned)k && gt < (unsigned)k) { s_bin = tid; s_k = k - (int)gt; }
        }
        __syncthreads();
        prefix |= ((unsigned)s_bin) << shift;
        k = s_k;
        __syncthreads();
    }
    return u2f(prefix);
}

// ---------------- speculative copy: out_W = W (starts at t=0, no deps) ----------------
__global__ void copy_W_kernel(const float* __restrict__ W, float* __restrict__ out) {
    size_t idx = ((size_t)blockIdx.x * blockDim.x + threadIdx.x) * 4;
    float4 w = __ldcs(reinterpret_cast<const float4*>(W + idx));
    __stcs(reinterpret_cast<float4*>(out + idx), w);
}

// ---------------- K1: h1 = W_ei_ca3 @ x, h3 = W_ei_ca1 @ x (one warp/row) --------------
__global__ __launch_bounds__(256) void matvec_dual_kernel(
        const float* __restrict__ Wa, const float* __restrict__ Wb,
        const float* __restrict__ x) {
    int warp = threadIdx.x >> 5, lane = threadIdx.x & 31;
    int row = blockIdx.x * 8 + warp;
    const float* W; float* out; int r;
    if (row < DIM_CA3) { W = Wa; out = g_h1; r = row; }
    else               { W = Wb; out = g_h3; r = row - DIM_CA3; }
    const float4* w4 = reinterpret_cast<const float4*>(W) + (size_t)r * (DIM_EI / 4);
    const float4* x4 = reinterpret_cast<const float4*>(x);
    float acc = 0.0f;
    #pragma unroll 8
    for (int i = lane; i < DIM_EI / 4; i += 32) {
        float4 w = __ldcs(&w4[i]);
        float4 v = __ldg(&x4[i]);
        acc += w.x * v.x + w.y * v.y + w.z * v.z + w.w * v.w;
    }
    #pragma unroll
    for (int o = 16; o; o >>= 1) acc += __shfl_down_sync(0xffffffffu, acc, o);
    if (lane == 0) out[r] = acc;
}

// ---------------- K2: block0 -> top-2(h1)+x_ca3+nnz compaction;
//                      block1 -> top-100(h3)+IS+active-row compaction ------------------
__global__ void stageA_kernel() {
    __shared__ int wsum[32];
    int lane = threadIdx.x & 31, wid = threadIdx.x >> 5;
    int base = threadIdx.x * 8;
    const float* src = (blockIdx.x == 0) ? g_h1 : g_h3;
    int K = (blockIdx.x == 0) ? 2 : 100;

    float xv[8]; unsigned uv[8];
    #pragma unroll
    for (int j = 0; j < 8; j++) { xv[j] = src[base + j]; uv[j] = f2u(xv[j]); }
    float th = kth_largest_radix256<8>(uv, K);

    float vals[8]; int keep[8]; int cnt = 0;
    #pragma unroll
    for (int j = 0; j < 8; j++) {
        int kp = (xv[j] >= th);
        float v = kp ? sigm(BETA * (xv[j] - th)) : 0.0f;
        vals[j] = v; keep[j] = kp; cnt += kp;
        if (blockIdx.x == 0) g_xca3[base + j] = v;
        else                 g_IS[base + j]   = v;
    }
    // deterministic compaction: warp inclusive scan + 32-warp block scan
    int incl = cnt;
    #pragma unroll
    for (int o = 1; o < 32; o <<= 1) {
        int n = __shfl_up_sync(0xffffffffu, incl, o);
        if (lane >= o) incl += n;
    }
    if (lane == 31) wsum[wid] = incl;
    __syncthreads();
    if (threadIdx.x == 0) {
        int s = 0;
        #pragma unroll
        for (int i = 0; i < 32; i++) { int c = wsum[i]; wsum[i] = s; s += c; }
        if (blockIdx.x == 0) g_nnz_cnt = s;
        else                 g_act_cnt = s;
    }
    __syncthreads();
    int off = wsum[wid] + incl - cnt;
    if (blockIdx.x == 0) {
        #pragma unroll
        for (int j = 0; j < 8; j++)
            if (keep[j]) { g_nnz_idx[off] = base + j; g_nnz_val[off] = vals[j]; ++off; }
    } else {
        #pragma unroll
        for (int j = 0; j < 8; j++)
            if (keep[j]) { g_act_idx[off] = base + j; ++off; }
    }
}

// ---------------- K3: fused h2 gather (~2 nnz) + top-100 + dense sigmoid --------------
__global__ void stageBC_kernel(const float* __restrict__ W3) {
    int cnt = g_nnz_cnt;
    int base = threadIdx.x * 8;
    float hv[8]; unsigned uv[8];
    #pragma unroll
    for (int r = 0; r < 8; r++) {
        size_t rowoff = (size_t)(base + r) * DIM_CA3;
        float acc = 0.0f;
        for (int k = 0; k < cnt; k++)
            acc += W3[rowoff + g_nnz_idx[k]] * g_nnz_val[k];
        hv[r] = acc; uv[r] = f2u(acc);
    }
    float th = kth_largest_radix256<8>(uv, 100);
    #pragma unroll
    for (int r = 0; r < 8; r++)
        g_xca1[base + r] = sigm(BETA * (hv[r] - th));   // flag=False: no hard mask
}

// ---------------- K4: h4 = W_ca1_eo @ x_ca1; last block: top-50 + masked sigmoid ------
__global__ __launch_bounds__(256) void matvec_out_kernel(
        const float* __restrict__ W, float* __restrict__ out) {
    int warp = threadIdx.x >> 5, lane = threadIdx.x & 31;
    int tid = threadIdx.x;
    int row = blockIdx.x * 8 + warp;
    const float4* w4 = reinterpret_cast<const float4*>(W) + (size_t)row * (DIM_CA1 / 4);
    const float4* x4 = reinterpret_cast<const float4*>(g_xca1);
    float acc = 0.0f;
    #pragma unroll 8
    for (int i = lane; i < DIM_CA1 / 4; i += 32) {
        float4 w = __ldcs(&w4[i]);
        float4 v = __ldg(&x4[i]);
        acc += w.x * v.x + w.y * v.y + w.z * v.z + w.w * v.w;
    }
    #pragma unroll
    for (int o = 16; o; o >>= 1) acc += __shfl_down_sync(0xffffffffu, acc, o);
    if (lane == 0) {
        g_h4[row] = acc;
        __threadfence();
    }
    __syncthreads();
    __shared__ bool s_last;
    if (tid == 0) {
        unsigned t = atomicAdd(&g_ctr_out, 1u);
        s_last = (t == gridDim.x - 1);
    }
    __syncthreads();
    if (!s_last) return;
    __threadfence();
    float th = kth_global_256(g_h4, DIM_EO, 50);
    for (int i = tid; i < DIM_EO; i += 256) {
        float xx = g_h4[i];
        out[i] = (xx >= th) ? sigm(BETA * (xx - th)) : 0.0f;
    }
    if (tid == 0) g_ctr_out = 0;   // self-reset for graph replay
}

// ---------------- K5: fixup the ~100 rows with IS > 0 (after copy completes) ----------
__global__ void fixup_W_kernel(const float* __restrict__ W, float* __restrict__ out) {
    int nact = g_act_cnt;
    for (int a = blockIdx.x; a < nact; a += gridDim.x) {
        int row = g_act_idx[a];
        float s = g_IS[row];
        float ca = 1.0f - s * ALPHA;
        float cb = ALPHA * s;
        const float4* w4  = reinterpret_cast<const float4*>(W)   + (size_t)row * (DIM_CA3 / 4);
        float4*       o4  = reinterpret_cast<float4*>(out)       + (size_t)row * (DIM_CA3 / 4);
        const float4* xc4 = reinterpret_cast<const float4*>(g_xca3);
        for (int j = threadIdx.x; j < DIM_CA3 / 4; j += blockDim.x) {
            float4 w = w4[j], xc = xc4[j];
            float4 o;
            o.x = ca * w.x + cb * xc.x;
            o.y = ca * w.y + cb * xc.y;
            o.z = ca * w.z + cb * xc.z;
            o.w = ca * w.w + cb * xc.w;
            o4[j] = o;
        }
    }
}

// ---------------- launch: copy at t=0 on s1, compute chain on s0, join, fixup ---------
extern "C" void kernel_launch(void* const* d_in, const int* in_sizes, int n_in,
                              void* d_out, int out_size) {
    const float* x_ei      = (const float*)d_in[0];
    const float* W_ei_ca3  = (const float*)d_in[1];
    const float* W_ei_ca1  = (const float*)d_in[2];
    const float* W_ca3_ca1 = (const float*)d_in[3];
    const float* W_ca1_eo  = (const float*)d_in[4];
    float* out = (float*)d_out;

    cudaStream_t s1;
    cudaStreamCreateWithFlags(&s1, cudaStreamNonBlocking);
    cudaEvent_t e_fork, e_join;
    cudaEventCreateWithFlags(&e_fork, cudaEventDisableTiming);
    cudaEventCreateWithFlags(&e_join, cudaEventDisableTiming);

    // fork immediately: speculative W copy has no dependencies
    cudaEventRecord(e_fork, 0);
    cudaStreamWaitEvent(s1, e_fork, 0);
    copy_W_kernel<<<(unsigned)((size_t)DIM_CA1 * DIM_CA3 / 4 / 256), 256, 0, s1>>>(
        W_ca3_ca1, out + DIM_EO);

    // compute chain on stream 0 (shares DRAM BW with the copy)
    matvec_dual_kernel<<<(DIM_CA3 + DIM_CA1) / 8, 256>>>(W_ei_ca3, W_ei_ca1, x_ei);
    stageA_kernel<<<2, 1024>>>();
    stageBC_kernel<<<1, 1024>>>(W_ca3_ca1);
    matvec_out_kernel<<<DIM_EO / 8, 256>>>(W_ca1_eo, out);

    // join: fixup overwrites the IS>0 rows, so it must follow the copy
    cudaEventRecord(e_join, s1);
    cudaStreamWaitEvent(0, e_join, 0);
    fixup_W_kernel<<<128, 256>>>(W_ca3_ca1, out + DIM_EO);

    cudaEventDestroy(e_fork);
    cudaEventDestroy(e_join);
    cudaStreamDestroy(s1);
}

// round 8
// speedup vs baseline: 1.1159x; 1.1159x over previous
#include <cuda_runtime.h>
#include <math.h>

#define DIM_EI  4096
#define DIM_CA3 8192
#define DIM_CA1 8192
#define DIM_EO  4096

static constexpr float BETA  = 10.0f;
static constexpr float ALPHA = 0.01f;

// ---------------- device scratch ----------------
__device__ float g_h1[DIM_CA3];
__device__ float g_h3[DIM_CA1];
__device__ float g_h2[DIM_CA1];
__device__ float g_h4[DIM_EO];
__device__ float g_xca3[DIM_CA3];
__device__ float g_IS[DIM_CA1];
__device__ float g_xca1[DIM_CA1];
__device__ int   g_nnz_idx[DIM_CA3];
__device__ float g_nnz_val[DIM_CA3];
__device__ int   g_nnz_cnt;
__device__ unsigned g_ctr_out;   // zero-init; self-resets each replay

// ---------------- helpers ----------------
__device__ __forceinline__ unsigned f2u(float f) {
    unsigned u = __float_as_uint(f);
    return (u & 0x80000000u) ? ~u : (u | 0x80000000u);
}
__device__ __forceinline__ float u2f(unsigned u) {
    return __uint_as_float((u & 0x80000000u) ? (u & 0x7fffffffu) : ~u);
}
__device__ __forceinline__ float sigm(float z) { return 1.0f / (1.0f + expf(-z)); }

// Exact K-th largest via 4-pass radix-256 over per-thread register values.
// blockDim.x >= 256; all threads call.
template<int M>
__device__ float kth_largest_radix256(const unsigned* uv, int K) {
    __shared__ unsigned s_hist[256];
    __shared__ int s_bin, s_k;
    unsigned prefix = 0;
    int k = K;
    #pragma unroll
    for (int shift = 24; shift >= 0; shift -= 8) {
        for (int b = threadIdx.x; b < 256; b += blockDim.x) s_hist[b] = 0;
        __syncthreads();
        unsigned hi = (shift == 24) ? 0u : (0xFFFFFFFFu << (shift + 8));
        #pragma unroll
        for (int j = 0; j < M; j++) {
            unsigned u = uv[j];
            if ((u & hi) == prefix) atomicAdd(&s_hist[(u >> shift) & 255], 1u);
        }
        __syncthreads();
        #pragma unroll
        for (int d = 1; d < 256; d <<= 1) {
            unsigned add = 0;
            if (threadIdx.x < 256)
                add = (threadIdx.x + d < 256) ? s_hist[threadIdx.x + d] : 0u;
            __syncthreads();
            if (threadIdx.x < 256) s_hist[threadIdx.x] += add;
            __syncthreads();
        }
        if (threadIdx.x < 256) {
            unsigned ge = s_hist[threadIdx.x];
            unsigned gt = (threadIdx.x == 255) ? 0u : s_hist[threadIdx.x + 1];
            if (ge >= (unsigned)k && gt < (unsigned)k) { s_bin = threadIdx.x; s_k = k - (int)gt; }
        }
        __syncthreads();
        prefix |= ((unsigned)s_bin) << shift;
        k = s_k;
        __syncthreads();
    }
    return u2f(prefix);
}

// K-th largest of x[0..n), global-read variant (256 threads).
__device__ float kth_global_256(const float* __restrict__ x, int n, int K) {
    __shared__ unsigned s_hist[256];
    __shared__ int s_bin, s_k;
    int tid = threadIdx.x;
    unsigned prefix = 0;
    int k = K;
    #pragma unroll
    for (int shift = 24; shift >= 0; shift -= 8) {
        s_hist[tid] = 0;
        __syncthreads();
        unsigned hi = (shift == 24) ? 0u : (0xFFFFFFFFu << (shift + 8));
        for (int i = tid; i < n; i += 256) {
            unsigned u = f2u(x[i]);
            if ((u & hi) == prefix) atomicAdd(&s_hist[(u >> shift) & 255], 1u);
        }
        __syncthreads();
        #pragma unroll
        for (int d = 1; d < 256; d <<= 1) {
            unsigned add = (tid + d < 256) ? s_hist[tid + d] : 0u;
            __syncthreads();
            s_hist[tid] += add;
            __syncthreads();
        }
        {
            unsigned ge = s_hist[tid];
            unsigned gt = (tid == 255) ? 0u : s_hist[tid + 1];
            if (ge >= (unsigned)k && gt < (unsigned)k) { s_bin = tid; s_k = k - (int)gt; }
        }
        __syncthreads();
        prefix |= ((unsigned)s_bin) << shift;
        k = s_k;
        __syncthreads();
    }
    return u2f(prefix);
}

// ---------------- half matvec: target selected INSIDE device code ----------------
// which==0 -> g_h1, which==1 -> g_h3  (never pass __device__ symbols from host!)
__global__ __launch_bounds__(256) void matvec_half_kernel(
        const float* __restrict__ W, const float* __restrict__ x, int which) {
    int warp = threadIdx.x >> 5, lane = threadIdx.x & 31;
    int r = blockIdx.x * 8 + warp;
    float* outv = which ? g_h3 : g_h1;
    const float4* w4 = reinterpret_cast<const float4*>(W) + (size_t)r * (DIM_EI / 4);
    const float4* x4 = reinterpret_cast<const float4*>(x);
    float acc = 0.0f;
    #pragma unroll 8
    for (int i = lane; i < DIM_EI / 4; i += 32) {
        float4 w = __ldcs(&w4[i]);
        float4 v = __ldg(&x4[i]);
        acc += w.x * v.x + w.y * v.y + w.z * v.z + w.w * v.w;
    }
    #pragma unroll
    for (int o = 16; o; o >>= 1) acc += __shfl_down_sync(0xffffffffu, acc, o);
    if (lane == 0) outv[r] = acc;
}

// ---------------- stageA0: top-2(h1) -> x_ca3 + nnz compaction (1 block, 1024 thr) ----
__global__ void stageA0_kernel() {
    __shared__ int wsum[32];
    int lane = threadIdx.x & 31, wid = threadIdx.x >> 5;
    int base = threadIdx.x * 8;
    float xv[8]; unsigned uv[8];
    #pragma unroll
    for (int j = 0; j < 8; j++) { xv[j] = g_h1[base + j]; uv[j] = f2u(xv[j]); }
    float th = kth_largest_radix256<8>(uv, 2);
    float vals[8]; int keep[8]; int cnt = 0;
    #pragma unroll
    for (int j = 0; j < 8; j++) {
        int kp = (xv[j] >= th);
        float v = kp ? sigm(BETA * (xv[j] - th)) : 0.0f;
        g_xca3[base + j] = v;
        vals[j] = v; keep[j] = kp; cnt += kp;
    }
    int incl = cnt;
    #pragma unroll
    for (int o = 1; o < 32; o <<= 1) {
        int n = __shfl_up_sync(0xffffffffu, incl, o);
        if (lane >= o) incl += n;
    }
    if (lane == 31) wsum[wid] = incl;
    __syncthreads();
    if (threadIdx.x == 0) {
        int s = 0;
        #pragma unroll
        for (int i = 0; i < 32; i++) { int c = wsum[i]; wsum[i] = s; s += c; }
        g_nnz_cnt = s;
    }
    __syncthreads();
    int off = wsum[wid] + incl - cnt;
    #pragma unroll
    for (int j = 0; j < 8; j++)
        if (keep[j]) { g_nnz_idx[off] = base + j; g_nnz_val[off] = vals[j]; ++off; }
}

// ---------------- stageA1: top-100(h3) -> IS (1 block, 1024 thr) ----------------------
__global__ void stageA1_kernel() {
    int base = threadIdx.x * 8;
    float xv[8]; unsigned uv[8];
    #pragma unroll
    for (int j = 0; j < 8; j++) { xv[j] = g_h3[base + j]; uv[j] = f2u(xv[j]); }
    float th = kth_largest_radix256<8>(uv, 100);
    #pragma unroll
    for (int j = 0; j < 8; j++)
        g_IS[base + j] = (xv[j] >= th) ? sigm(BETA * (xv[j] - th)) : 0.0f;
}

// ---------------- gather h2 across 32 blocks (spreads L1tex wavefront pressure) -------
__global__ void gather_h2_kernel(const float* __restrict__ W3) {
    int i = blockIdx.x * blockDim.x + threadIdx.x;   // one row per thread (32x256=8192)
    int cnt = g_nnz_cnt;
    size_t rowoff = (size_t)i * DIM_CA3;
    float acc = 0.0f;
    for (int k = 0; k < cnt; k++)
        acc += __ldg(&W3[rowoff + g_nnz_idx[k]]) * g_nnz_val[k];
    g_h2[i] = acc;
}

// ---------------- stageC: top-100(h2) + dense sigmoid -> x_ca1 (1 block, 1024 thr) ----
__global__ void stageC_kernel() {
    int base = threadIdx.x * 8;
    float xv[8]; unsigned uv[8];
    #pragma unroll
    for (int j = 0; j < 8; j++) { xv[j] = g_h2[base + j]; uv[j] = f2u(xv[j]); }
    float th = kth_largest_radix256<8>(uv, 100);
    #pragma unroll
    for (int j = 0; j < 8; j++)
        g_xca1[base + j] = sigm(BETA * (xv[j] - th));   // flag=False: no hard mask
}

// ---------------- update_W: (1-IS*a)*W + a*IS*x_ca3^T ----------------
__global__ void update_W_kernel(const float* __restrict__ W, float* __restrict__ out) {
    size_t idx = ((size_t)blockIdx.x * blockDim.x + threadIdx.x) * 4;
    int row = (int)(idx >> 13);
    int col = (int)(idx & (DIM_CA3 - 1));
    float s = g_IS[row];
    float a = 1.0f - s * ALPHA;
    float b = ALPHA * s;
    float4 w  = __ldcs(reinterpret_cast<const float4*>(W + idx));
    float4 xc = *reinterpret_cast<const float4*>(g_xca3 + col);
    float4 o;
    o.x = a * w.x + b * xc.x;
    o.y = a * w.y + b * xc.y;
    o.z = a * w.z + b * xc.z;
    o.w = a * w.w + b * xc.w;
    __stcs(reinterpret_cast<float4*>(out + idx), o);
}

// ---------------- matvec_out + fused top-50 tail ----------------
__global__ __launch_bounds__(256) void matvec_out_kernel(
        const float* __restrict__ W, float* __restrict__ out) {
    int warp = threadIdx.x >> 5, lane = threadIdx.x & 31;
    int tid = threadIdx.x;
    int row = blockIdx.x * 8 + warp;
    const float4* w4 = reinterpret_cast<const float4*>(W) + (size_t)row * (DIM_CA1 / 4);
    const float4* x4 = reinterpret_cast<const float4*>(g_xca1);
    float acc = 0.0f;
    #pragma unroll 8
    for (int i = lane; i < DIM_CA1 / 4; i += 32) {
        float4 w = __ldcs(&w4[i]);
        float4 v = __ldg(&x4[i]);
        acc += w.x * v.x + w.y * v.y + w.z * v.z + w.w * v.w;
    }
    #pragma unroll
    for (int o = 16; o; o >>= 1) acc += __shfl_down_sync(0xffffffffu, acc, o);
    if (lane == 0) {
        g_h4[row] = acc;
        __threadfence();
    }
    __syncthreads();
    __shared__ bool s_last;
    if (tid == 0) {
        unsigned t = atomicAdd(&g_ctr_out, 1u);
        s_last = (t == gridDim.x - 1);
    }
    __syncthreads();
    if (!s_last) return;
    __threadfence();
    float th = kth_global_256(g_h4, DIM_EO, 50);
    for (int i = tid; i < DIM_EO; i += 256) {
        float xx = g_h4[i];
        out[i] = (xx >= th) ? sigm(BETA * (xx - th)) : 0.0f;
    }
    if (tid == 0) g_ctr_out = 0;
}

// ---------------- launch ----------------
// s0: mv(h1) [e_h1] -> mv(h3) -> stageA1(IS) -> wait(e_A0) -> update_W -> wait(e_join)
// s1: wait(e_h1) -> stageA0 [e_A0] -> gather_h2 -> stageC -> matvec_out [e_join]
extern "C" void kernel_launch(void* const* d_in, const int* in_sizes, int n_in,
                              void* d_out, int out_size) {
    const float* x_ei      = (const float*)d_in[0];
    const float* W_ei_ca3  = (const float*)d_in[1];
    const float* W_ei_ca1  = (const float*)d_in[2];
    const float* W_ca3_ca1 = (const float*)d_in[3];
    const float* W_ca1_eo  = (const float*)d_in[4];
    float* out = (float*)d_out;

    cudaStream_t s1;
    cudaStreamCreateWithFlags(&s1, cudaStreamNonBlocking);
    cudaEvent_t e_h1, e_A0, e_join;
    cudaEventCreateWithFlags(&e_h1,   cudaEventDisableTiming);
    cudaEventCreateWithFlags(&e_A0,   cudaEventDisableTiming);
    cudaEventCreateWithFlags(&e_join, cudaEventDisableTiming);

    matvec_half_kernel<<<DIM_CA3 / 8, 256>>>(W_ei_ca3, x_ei, 0);
    cudaEventRecord(e_h1, 0);

    matvec_half_kernel<<<DIM_CA1 / 8, 256>>>(W_ei_ca1, x_ei, 1);
    stageA1_kernel<<<1, 1024>>>();

    // s1: stageA0 + B-chain, overlapping mv(h3)/stageA1/update_W on s0
    cudaStreamWaitEvent(s1, e_h1, 0);
    stageA0_kernel<<<1, 1024, 0, s1>>>();
    cudaEventRecord(e_A0, s1);
    gather_h2_kernel<<<32, 256, 0, s1>>>(W_ca3_ca1);
    stageC_kernel<<<1, 1024, 0, s1>>>();
    matvec_out_kernel<<<DIM_EO / 8, 256, 0, s1>>>(W_ca1_eo, out);
    cudaEventRecord(e_join, s1);

    // update_W needs IS (stageA1, in-stream) and x_ca3 (stageA0 via e_A0)
    cudaStreamWaitEvent(0, e_A0, 0);
    update_W_kernel<<<(unsigned)((size_t)DIM_CA1 * DIM_CA3 / 4 / 256), 256>>>(W_ca3_ca1, out + DIM_EO);

    cudaStreamWaitEvent(0, e_join, 0);

    cudaEventDestroy(e_h1);
    cudaEventDestroy(e_A0);
    cudaEventDestroy(e_join);
    cudaStreamDestroy(s1);
}